// round 2
// baseline (speedup 1.0000x reference)
#include <cuda_runtime.h>

#define BB 2
#define NN 262144
#define SS 24
#define TOT (BB*NN)
#define EPSV 1e-4f

// ---- scratch (no allocation allowed; __device__ globals) ----
__device__ float g_wm[TOT];
__device__ float g_u[TOT];
__device__ float g_v[TOT];
__device__ double g_sums[3];   // [0]=sum|A|, [1]=sum(valid), [2]=sum(diff^2)

// ---------------------------------------------------------------------------
__device__ __forceinline__ float blockReduceSum(float v) {
    __shared__ float sh[32];
    int lane = threadIdx.x & 31;
    int wid  = threadIdx.x >> 5;
    #pragma unroll
    for (int o = 16; o > 0; o >>= 1) v += __shfl_down_sync(0xffffffffu, v, o);
    if (lane == 0) sh[wid] = v;
    __syncthreads();
    int nw = blockDim.x >> 5;
    v = (threadIdx.x < nw) ? sh[threadIdx.x] : 0.f;
    if (wid == 0) {
        #pragma unroll
        for (int o = 16; o > 0; o >>= 1) v += __shfl_down_sync(0xffffffffu, v, o);
    }
    return v;
}

// ---------------------------------------------------------------------------
__global__ void k_zero() {
    if (threadIdx.x < 3) g_sums[threadIdx.x] = 0.0;
}

// wm = w*mask ; u_init = wm * G[:,0] ; reduce |A| and valid-count
__global__ void k_init(const float* __restrict__ G,
                       const float* __restrict__ Ad,
                       const float* __restrict__ Ao,
                       const float* __restrict__ w,
                       const float* __restrict__ vm) {
    int i = blockIdx.x * blockDim.x + threadIdx.x;
    float absA = 0.f, valid = 0.f;
    if (i < TOT) {
        float v   = vm[i];
        float wmv = w[i] * v;
        g_wm[i] = wmv;
        g_u[i]  = wmv * G[(long long)i * 25];
        absA = fabsf(Ad[i]);
        const float* ao = Ao + (long long)i * SS;
        #pragma unroll
        for (int j = 0; j < SS; j++) absA += fabsf(ao[j]);
        valid = v;
    }
    float ba = blockReduceSum(absA);
    if (threadIdx.x == 0) atomicAdd(&g_sums[0], (double)ba);
    __syncthreads();
    float bv = blockReduceSum(valid);
    if (threadIdx.x == 0) atomicAdd(&g_sums[1], (double)bv);
}

// u += G^T scatter: one thread per edge
__global__ void k_scatter(const float* __restrict__ G,
                          const int* __restrict__ nbr) {
    long long t = (long long)blockIdx.x * blockDim.x + threadIdx.x;
    if (t >= (long long)TOT * SS) return;
    int i = (int)(t / SS);
    int j = (int)(t - (long long)i * SS);
    int nb = nbr[t];
    if ((unsigned)nb < (unsigned)NN) {
        int base = (i >= NN) ? NN : 0;
        float val = g_wm[i] * G[(long long)i * 25 + 1 + j];
        atomicAdd(&g_u[base + nb], val);
    }
}

// v = G u + eps*wm  (gather)
__global__ void k_gather_v(const float* __restrict__ G,
                           const int* __restrict__ nbr) {
    int i = blockIdx.x * blockDim.x + threadIdx.x;
    if (i >= TOT) return;
    int base = (i >= NN) ? NN : 0;
    const float* gc = G   + (long long)i * 25;
    const int*   nb = nbr + (long long)i * SS;
    float acc = g_u[i] * gc[0];
    #pragma unroll
    for (int j = 0; j < SS; j++) {
        int n = nb[j];
        if ((unsigned)n < (unsigned)NN)
            acc += g_u[base + n] * gc[1 + j];
    }
    g_v[i] = acc + EPSV * g_wm[i];
}

// y = A v ; z = y/norm ; accumulate diff^2
__global__ void k_gather_y(const float* __restrict__ Ad,
                           const float* __restrict__ Ao,
                           const float* __restrict__ vm,
                           const int* __restrict__ nbr) {
    int i = blockIdx.x * blockDim.x + threadIdx.x;
    float d2 = 0.f;
    if (i < TOT) {
        int base = (i >= NN) ? NN : 0;
        const float* ao = Ao  + (long long)i * SS;
        const int*   nb = nbr + (long long)i * SS;
        float acc = g_v[i] * Ad[i];
        #pragma unroll
        for (int j = 0; j < SS; j++) {
            int n = nb[j];
            if ((unsigned)n < (unsigned)NN)
                acc += g_v[base + n] * ao[j];
        }
        double norm = g_sums[0] / (g_sums[1] * 25.0 + 1e-6);
        float z = acc / (float)(norm + 1e-8);
        float diff = (z - g_wm[i]) * vm[i];
        d2 = diff * diff;
    }
    float s = blockReduceSum(d2);
    if (threadIdx.x == 0) atomicAdd(&g_sums[2], (double)s);
}

__global__ void k_final(float* out) {
    out[0] = (float)(g_sums[2] / (g_sums[1] + 1e-6));
}

// ---------------------------------------------------------------------------
extern "C" void kernel_launch(void* const* d_in, const int* in_sizes, int n_in,
                              void* d_out, int out_size) {
    const float* G   = (const float*)d_in[0];   // [2,N,25]
    const float* Ad  = (const float*)d_in[1];   // [2,N,1]
    const float* Ao  = (const float*)d_in[2];   // [2,N,24]
    const float* w   = (const float*)d_in[3];   // [2,N,1]
    const float* vm  = (const float*)d_in[4];   // [2,N,1]
    const int*   nbr = (const int*)d_in[5];     // [2,N,24] int32 (JAX x64 disabled)
    float* out = (float*)d_out;

    const int T = 256;
    const int nodeBlocks = (TOT + T - 1) / T;
    const long long edges = (long long)TOT * SS;
    const int edgeBlocks = (int)((edges + T - 1) / T);

    k_zero<<<1, 32>>>();
    k_init<<<nodeBlocks, T>>>(G, Ad, Ao, w, vm);
    k_scatter<<<edgeBlocks, T>>>(G, nbr);
    k_gather_v<<<nodeBlocks, T>>>(G, nbr);
    k_gather_y<<<nodeBlocks, T>>>(Ad, Ao, vm, nbr);
    k_final<<<1, 1>>>(out);
}

// round 3
// speedup vs baseline: 1.1122x; 1.1122x over previous
#include <cuda_runtime.h>

#define BB 2
#define NN 262144
#define SS 24
#define TOT (BB*NN)
#define EPSV 1e-4f
#define PAD 257

// ---- scratch (no allocation allowed; __device__ globals) ----
__device__ float g_wm[TOT];
__device__ float g_u[TOT];
__device__ float g_v[TOT];
__device__ double g_sums[3];   // [0]=sum|A|, [1]=sum(valid), [2]=sum(diff^2)

// ---------------------------------------------------------------------------
__device__ __forceinline__ float blockReduceSum(float v) {
    __shared__ float sh[32];
    int lane = threadIdx.x & 31;
    int wid  = threadIdx.x >> 5;
    #pragma unroll
    for (int o = 16; o > 0; o >>= 1) v += __shfl_down_sync(0xffffffffu, v, o);
    if (lane == 0) sh[wid] = v;
    __syncthreads();
    int nw = blockDim.x >> 5;
    v = (threadIdx.x < nw) ? sh[threadIdx.x] : 0.f;
    if (wid == 0) {
        #pragma unroll
        for (int o = 16; o > 0; o >>= 1) v += __shfl_down_sync(0xffffffffu, v, o);
    }
    return v;
}

__global__ void k_zero() {
    if (threadIdx.x < 3) g_sums[threadIdx.x] = 0.0;
}

// wm = w*mask ; g_u = wm*G0 (plain store, covers all elems) ; flat |A| + valid reductions
__global__ __launch_bounds__(256) void k_init(const float* __restrict__ G,
                                              const float* __restrict__ Ad,
                                              const float* __restrict__ Ao,
                                              const float* __restrict__ w,
                                              const float* __restrict__ vm) {
    int i = blockIdx.x * blockDim.x + threadIdx.x;   // exact grid: 2048*256 = TOT
    float v   = vm[i];
    float wmv = w[i] * v;
    g_wm[i] = wmv;
    g_u[i]  = wmv * G[(long long)i * 25];

    float s = fabsf(Ad[i]);
    const float4* A4 = (const float4*)Ao;            // 12.58M floats = TOT*6 float4
    #pragma unroll
    for (int k = 0; k < 6; k++) {
        float4 a = A4[(long long)k * TOT + i];
        s += fabsf(a.x) + fabsf(a.y) + fabsf(a.z) + fabsf(a.w);
    }
    float ba = blockReduceSum(s);
    if (threadIdx.x == 0) atomicAdd(&g_sums[0], (double)ba);
    __syncthreads();
    float bv = blockReduceSum(v);
    if (threadIdx.x == 0) atomicAdd(&g_sums[1], (double)bv);
}

// u += G^T scatter: one thread per edge (coalesced reads, RED.F32 spread atomics)
__global__ __launch_bounds__(256) void k_scatter(const float* __restrict__ G,
                                                 const int* __restrict__ nbr) {
    long long t = (long long)blockIdx.x * blockDim.x + threadIdx.x;  // exact: edges
    int i = (int)(t / SS);
    int j = (int)(t - (long long)i * SS);
    int nb = nbr[t];
    if ((unsigned)nb < (unsigned)NN) {
        int base = (i >= NN) ? NN : 0;
        float val = g_wm[i] * G[(long long)i * 25 + 1 + j];
        atomicAdd(&g_u[base + nb], val);
    }
}

// v = G u + eps*wm : G staged transposed in smem, nbr via int4, batched gathers
__global__ __launch_bounds__(256) void k_gather_v(const float* __restrict__ G,
                                                  const int* __restrict__ nbr) {
    __shared__ float sh_g[25 * PAD];
    int tid = threadIdx.x;
    int node0 = blockIdx.x * 256;

    const float* gBase = G + (long long)node0 * 25;
    #pragma unroll
    for (int k = 0; k < 25; k++) {
        int t = k * 256 + tid;
        sh_g[(t % 25) * PAD + t / 25] = gBase[t];
    }
    __syncthreads();

    int i = node0 + tid;
    int base = (i >= NN) ? NN : 0;

    int nn[24];
    const int4* nb4 = (const int4*)(nbr + (long long)i * SS);
    #pragma unroll
    for (int k = 0; k < 6; k++) {
        int4 q = nb4[k];
        nn[4*k+0] = q.x; nn[4*k+1] = q.y; nn[4*k+2] = q.z; nn[4*k+3] = q.w;
    }
    float xs[24];
    #pragma unroll
    for (int j = 0; j < SS; j++)
        xs[j] = ((unsigned)nn[j] < (unsigned)NN) ? g_u[base + nn[j]] : 0.f;

    float acc = g_u[i] * sh_g[tid];
    #pragma unroll
    for (int j = 0; j < SS; j++)
        acc = fmaf(xs[j], sh_g[(j + 1) * PAD + tid], acc);

    g_v[i] = acc + EPSV * g_wm[i];
}

// y = A v ; z = y/norm ; accumulate diff^2 : Ao staged transposed, nbr via int4
__global__ __launch_bounds__(256) void k_gather_y(const float* __restrict__ Ad,
                                                  const float* __restrict__ Ao,
                                                  const float* __restrict__ vm,
                                                  const int* __restrict__ nbr) {
    __shared__ float sh_a[24 * PAD];
    __shared__ float s_inv;
    int tid = threadIdx.x;
    int node0 = blockIdx.x * 256;

    const float* aBase = Ao + (long long)node0 * SS;
    #pragma unroll
    for (int k = 0; k < 24; k++) {
        int t = k * 256 + tid;
        sh_a[(t % 24) * PAD + t / 24] = aBase[t];
    }
    if (tid == 0) {
        double norm = g_sums[0] / (g_sums[1] * 25.0 + 1e-6);
        s_inv = (float)(1.0 / (norm + 1e-8));
    }
    __syncthreads();

    int i = node0 + tid;
    int base = (i >= NN) ? NN : 0;

    int nn[24];
    const int4* nb4 = (const int4*)(nbr + (long long)i * SS);
    #pragma unroll
    for (int k = 0; k < 6; k++) {
        int4 q = nb4[k];
        nn[4*k+0] = q.x; nn[4*k+1] = q.y; nn[4*k+2] = q.z; nn[4*k+3] = q.w;
    }
    float xs[24];
    #pragma unroll
    for (int j = 0; j < SS; j++)
        xs[j] = ((unsigned)nn[j] < (unsigned)NN) ? g_v[base + nn[j]] : 0.f;

    float acc = g_v[i] * Ad[i];
    #pragma unroll
    for (int j = 0; j < SS; j++)
        acc = fmaf(xs[j], sh_a[j * PAD + tid], acc);

    float z = acc * s_inv;
    float d = (z - g_wm[i]) * vm[i];
    float s = blockReduceSum(d * d);
    if (tid == 0) atomicAdd(&g_sums[2], (double)s);
}

__global__ void k_final(float* out) {
    out[0] = (float)(g_sums[2] / (g_sums[1] + 1e-6));
}

// ---------------------------------------------------------------------------
extern "C" void kernel_launch(void* const* d_in, const int* in_sizes, int n_in,
                              void* d_out, int out_size) {
    const float* G   = (const float*)d_in[0];   // [2,N,25]
    const float* Ad  = (const float*)d_in[1];   // [2,N,1]
    const float* Ao  = (const float*)d_in[2];   // [2,N,24]
    const float* w   = (const float*)d_in[3];   // [2,N,1]
    const float* vm  = (const float*)d_in[4];   // [2,N,1]
    const int*   nbr = (const int*)d_in[5];     // [2,N,24] int32
    float* out = (float*)d_out;

    const int T = 256;
    const int nodeBlocks = TOT / T;                       // 2048, exact
    const int edgeBlocks = (int)(((long long)TOT * SS) / T);  // 49152, exact

    k_zero<<<1, 32>>>();
    k_init<<<nodeBlocks, T>>>(G, Ad, Ao, w, vm);
    k_scatter<<<edgeBlocks, T>>>(G, nbr);
    k_gather_v<<<nodeBlocks, T>>>(G, nbr);
    k_gather_y<<<nodeBlocks, T>>>(Ad, Ao, vm, nbr);
    k_final<<<1, 1>>>(out);
}

// round 4
// speedup vs baseline: 1.1360x; 1.0214x over previous
#include <cuda_runtime.h>

#define BB 2
#define NN 262144
#define SS 24
#define TOT (BB*NN)
#define EPSV 1e-4f
#define PAD 257

// ---- scratch (no allocation allowed; __device__ globals) ----
__device__ float g_wm[TOT];
__device__ float g_u[TOT];
__device__ float g_v[TOT];
__device__ double g_sums[3];   // [0]=sum|A|, [1]=sum(valid), [2]=sum(diff^2)

// ---------------------------------------------------------------------------
__device__ __forceinline__ float blockReduceSum(float v) {
    __shared__ float sh[32];
    int lane = threadIdx.x & 31;
    int wid  = threadIdx.x >> 5;
    #pragma unroll
    for (int o = 16; o > 0; o >>= 1) v += __shfl_down_sync(0xffffffffu, v, o);
    if (lane == 0) sh[wid] = v;
    __syncthreads();
    int nw = blockDim.x >> 5;
    v = (threadIdx.x < nw) ? sh[threadIdx.x] : 0.f;
    if (wid == 0) {
        #pragma unroll
        for (int o = 16; o > 0; o >>= 1) v += __shfl_down_sync(0xffffffffu, v, o);
    }
    return v;
}

// zero g_sums and g_u (float4 grid-stride; u accumulated by atomics later)
__global__ __launch_bounds__(256) void k_zero() {
    long long i = (long long)blockIdx.x * blockDim.x + threadIdx.x;
    if (i == 0) { g_sums[0] = 0.0; g_sums[1] = 0.0; g_sums[2] = 0.0; }
    float4* u4 = (float4*)g_u;
    if (i < TOT / 4) u4[i] = make_float4(0.f, 0.f, 0.f, 0.f);
}

// Fused: wm = w*vm ; u += diag + G^T scatter (atomics into zeroed g_u) ;
//        flat |A| and valid reductions. G row staged in smem (coalesced).
__global__ __launch_bounds__(256) void k_init_scatter(const float* __restrict__ G,
                                                      const float* __restrict__ Ad,
                                                      const float* __restrict__ Ao,
                                                      const float* __restrict__ w,
                                                      const float* __restrict__ vm,
                                                      const int* __restrict__ nbr) {
    __shared__ float sh_g[25 * PAD];
    int tid = threadIdx.x;
    int node0 = blockIdx.x * 256;

    const float* gBase = G + (long long)node0 * 25;
    #pragma unroll
    for (int k = 0; k < 25; k++) {
        int t = k * 256 + tid;
        sh_g[(t % 25) * PAD + t / 25] = gBase[t];
    }
    __syncthreads();

    int i = node0 + tid;
    int base = (i >= NN) ? NN : 0;

    float v   = vm[i];
    float wmv = w[i] * v;
    g_wm[i] = wmv;

    int nn[24];
    const int4* nb4 = (const int4*)(nbr + (long long)i * SS);
    #pragma unroll
    for (int k = 0; k < 6; k++) {
        int4 q = nb4[k];
        nn[4*k+0] = q.x; nn[4*k+1] = q.y; nn[4*k+2] = q.z; nn[4*k+3] = q.w;
    }

    atomicAdd(&g_u[i], wmv * sh_g[tid]);                 // diagonal
    #pragma unroll
    for (int j = 0; j < SS; j++) {
        int nb = nn[j];
        if ((unsigned)nb < (unsigned)NN)
            atomicAdd(&g_u[base + nb], wmv * sh_g[(j + 1) * PAD + tid]);
    }

    // flat |A| reduction (association-free, coalesced float4 over Ao)
    float s = fabsf(Ad[i]);
    const float4* A4 = (const float4*)Ao;                // TOT*6 float4 total
    #pragma unroll
    for (int k = 0; k < 6; k++) {
        float4 a = A4[(long long)k * TOT + i];
        s += fabsf(a.x) + fabsf(a.y) + fabsf(a.z) + fabsf(a.w);
    }
    float ba = blockReduceSum(s);
    if (tid == 0) atomicAdd(&g_sums[0], (double)ba);
    __syncthreads();
    float bv = blockReduceSum(v);
    if (tid == 0) atomicAdd(&g_sums[1], (double)bv);
}

// v = G u + eps*wm : G staged transposed in smem, nbr via int4, batched gathers
__global__ __launch_bounds__(256) void k_gather_v(const float* __restrict__ G,
                                                  const int* __restrict__ nbr) {
    __shared__ float sh_g[25 * PAD];
    int tid = threadIdx.x;
    int node0 = blockIdx.x * 256;

    const float* gBase = G + (long long)node0 * 25;
    #pragma unroll
    for (int k = 0; k < 25; k++) {
        int t = k * 256 + tid;
        sh_g[(t % 25) * PAD + t / 25] = gBase[t];
    }
    __syncthreads();

    int i = node0 + tid;
    int base = (i >= NN) ? NN : 0;

    int nn[24];
    const int4* nb4 = (const int4*)(nbr + (long long)i * SS);
    #pragma unroll
    for (int k = 0; k < 6; k++) {
        int4 q = nb4[k];
        nn[4*k+0] = q.x; nn[4*k+1] = q.y; nn[4*k+2] = q.z; nn[4*k+3] = q.w;
    }
    float xs[24];
    #pragma unroll
    for (int j = 0; j < SS; j++)
        xs[j] = ((unsigned)nn[j] < (unsigned)NN) ? g_u[base + nn[j]] : 0.f;

    float acc = g_u[i] * sh_g[tid];
    #pragma unroll
    for (int j = 0; j < SS; j++)
        acc = fmaf(xs[j], sh_g[(j + 1) * PAD + tid], acc);

    g_v[i] = acc + EPSV * g_wm[i];
}

// y = A v ; z = y/norm ; accumulate diff^2 : Ao staged transposed, nbr via int4
__global__ __launch_bounds__(256) void k_gather_y(const float* __restrict__ Ad,
                                                  const float* __restrict__ Ao,
                                                  const float* __restrict__ vm,
                                                  const int* __restrict__ nbr) {
    __shared__ float sh_a[24 * PAD];
    __shared__ float s_inv;
    int tid = threadIdx.x;
    int node0 = blockIdx.x * 256;

    const float* aBase = Ao + (long long)node0 * SS;
    #pragma unroll
    for (int k = 0; k < 24; k++) {
        int t = k * 256 + tid;
        sh_a[(t % 24) * PAD + t / 24] = aBase[t];
    }
    if (tid == 0) {
        double norm = g_sums[0] / (g_sums[1] * 25.0 + 1e-6);
        s_inv = (float)(1.0 / (norm + 1e-8));
    }
    __syncthreads();

    int i = node0 + tid;
    int base = (i >= NN) ? NN : 0;

    int nn[24];
    const int4* nb4 = (const int4*)(nbr + (long long)i * SS);
    #pragma unroll
    for (int k = 0; k < 6; k++) {
        int4 q = nb4[k];
        nn[4*k+0] = q.x; nn[4*k+1] = q.y; nn[4*k+2] = q.z; nn[4*k+3] = q.w;
    }
    float xs[24];
    #pragma unroll
    for (int j = 0; j < SS; j++)
        xs[j] = ((unsigned)nn[j] < (unsigned)NN) ? g_v[base + nn[j]] : 0.f;

    float acc = g_v[i] * Ad[i];
    #pragma unroll
    for (int j = 0; j < SS; j++)
        acc = fmaf(xs[j], sh_a[j * PAD + tid], acc);

    float z = acc * s_inv;
    float d = (z - g_wm[i]) * vm[i];
    float s = blockReduceSum(d * d);
    if (tid == 0) atomicAdd(&g_sums[2], (double)s);
}

__global__ void k_final(float* out) {
    out[0] = (float)(g_sums[2] / (g_sums[1] + 1e-6));
}

// ---------------------------------------------------------------------------
extern "C" void kernel_launch(void* const* d_in, const int* in_sizes, int n_in,
                              void* d_out, int out_size) {
    const float* G   = (const float*)d_in[0];   // [2,N,25]
    const float* Ad  = (const float*)d_in[1];   // [2,N,1]
    const float* Ao  = (const float*)d_in[2];   // [2,N,24]
    const float* w   = (const float*)d_in[3];   // [2,N,1]
    const float* vm  = (const float*)d_in[4];   // [2,N,1]
    const int*   nbr = (const int*)d_in[5];     // [2,N,24] int32
    float* out = (float*)d_out;

    const int T = 256;
    const int nodeBlocks = TOT / T;             // 2048, exact
    const int zeroBlocks = (TOT / 4 + T - 1) / T;

    k_zero<<<zeroBlocks, T>>>();
    k_init_scatter<<<nodeBlocks, T>>>(G, Ad, Ao, w, vm, nbr);
    k_gather_v<<<nodeBlocks, T>>>(G, nbr);
    k_gather_y<<<nodeBlocks, T>>>(Ad, Ao, vm, nbr);
    k_final<<<1, 1>>>(out);
}